// round 10
// baseline (speedup 1.0000x reference)
#include <cuda_runtime.h>
#include <cuda_fp16.h>
#include <cstdint>

// out[b,o] = sum_i f_{o,i}(tanh(x[b,i])), Chebyshev basis, T0 folded to bias.
// GEMM: M=16384, N=256, K=2048 (16 chunks of 128 = 8 k16 slices).
// R10: fp16-accumulate mma (m16n8k16.f16) with per-chunk promotion to fp32 —
//      tests whether the legacy tensor pipe runs f16-accum at 2x f32-accum.

#define BATCH   16384
#define IDIM    256
#define ODIM    256
#define CTAM    128
#define NCHUNK  16
#define PLANES  16
#define THREADS 256

#define A_PLANE 2064                        // 128 rows * 16B + 16B pad
#define A_STAGE (PLANES * A_PLANE)          // 33024
#define B_PLANE (ODIM * 16)                 // 4096
#define B_STAGE (PLANES * B_PLANE)          // 65536
#define SM_B    (2 * A_STAGE)               // 66048
#define SMEM_TOTAL (SM_B + 2 * B_STAGE)     // 197120

#define TWO_LOG2E 2.8853900817779268f

// Chebyshev-basis B operand: [chunk 16][plane 16][col 256][8 halves] = 1 MB
__device__ __align__(128) __half g_B[NCHUNK * PLANES * ODIM * 8];
__device__ float g_bias[ODIM];

__device__ __forceinline__ uint32_t s2u(const void* p) {
    return (uint32_t)__cvta_generic_to_shared(p);
}

// ---------------------------------------------------------------- prep kernel
__global__ void bern_prep(const float* __restrict__ weights,
                          const float* __restrict__ coeffs) {
    static const float M[9][9] = {
        { 1, -8,  28, -56,  70, -56,  28, -8,  1},
        { 1, -6,  14, -14,   0,  14, -14,  6, -1},
        { 1, -4,   4,   4, -10,   4,   4, -4,  1},
        { 1, -2,  -2,   6,   0,  -6,   2,  2, -1},
        { 1,  0,  -4,   0,   6,   0,  -4,  0,  1},
        { 1,  2,  -2,  -6,   0,   6,   2, -2, -1},
        { 1,  4,   4,  -4, -10,  -4,   4,  4,  1},
        { 1,  6,  14,  14,   0, -14, -14, -6, -1},
        { 1,  8,  28,  56,  70,  56,  28,  8,  1}
    };
    int o = blockIdx.x;
    int i = threadIdx.x;

    float w = weights[o * IDIM + i];
    const float* cf = coeffs + (size_t)(o * IDIM + i) * 9;
    float c[9];
#pragma unroll
    for (int k = 0; k < 9; k++) c[k] = cf[k] * w;

    float p[9];
#pragma unroll
    for (int n = 0; n < 9; n++) {
        float s = 0.0f;
#pragma unroll
        for (int k = 0; k < 9; k++) s += c[k] * M[k][n];
        p[n] = s;
    }
    float q0 = p[0] + 0.5f * p[2] + 0.375f * p[4] + 0.3125f * p[6] + 0.2734375f * p[8];
    float q1 = p[1] + 0.75f * p[3] + 0.625f * p[5] + 0.546875f * p[7];
    float q2 = 0.5f * p[2] + 0.5f * p[4] + 0.46875f * p[6] + 0.4375f * p[8];
    float q3 = 0.25f * p[3] + 0.3125f * p[5] + 0.328125f * p[7];
    float q4 = 0.125f * p[4] + 0.1875f * p[6] + 0.21875f * p[8];
    float q5 = 0.0625f * p[5] + 0.109375f * p[7];
    float q6 = 0.03125f * p[6] + 0.0625f * p[8];
    float q7 = 0.015625f * p[7];
    float q8 = 0.0078125f * p[8];

    uint32_t u[4];
    { __half2 h = __floats2half2_rn(q1, q2); u[0] = *reinterpret_cast<uint32_t*>(&h); }
    { __half2 h = __floats2half2_rn(q3, q4); u[1] = *reinterpret_cast<uint32_t*>(&h); }
    { __half2 h = __floats2half2_rn(q5, q6); u[2] = *reinterpret_cast<uint32_t*>(&h); }
    { __half2 h = __floats2half2_rn(q7, q8); u[3] = *reinterpret_cast<uint32_t*>(&h); }
    int cc = i >> 4, pl = i & 15;
    *reinterpret_cast<uint4*>(reinterpret_cast<char*>(g_B) +
        ((size_t)(cc * PLANES + pl) * ODIM + o) * 16) = make_uint4(u[0], u[1], u[2], u[3]);

    __shared__ float red[IDIM];
    red[i] = q0;
    __syncthreads();
#pragma unroll
    for (int st = IDIM / 2; st > 0; st >>= 1) {
        if (i < st) red[i] += red[i + st];
        __syncthreads();
    }
    if (i == 0) g_bias[o] = red[0];
}

// ---------------------------------------------------------------- main kernel
__global__ void __launch_bounds__(THREADS, 1)
bern_gemm(const float* __restrict__ x, float* __restrict__ out) {
    extern __shared__ char smem[];
    const int tid  = threadIdx.x;
    const int wid  = tid >> 5;
    const int lane = tid & 31;
    const int mbase = blockIdx.x * CTAM;
    const int wm = wid & 1;        // 2 warps along M (64 rows each)
    const int wn = wid >> 1;       // 4 warps along N (64 cols each)

    float acc[4][8][4];            // fp32 master accumulators
#pragma unroll
    for (int a = 0; a < 4; a++)
#pragma unroll
        for (int b = 0; b < 8; b++)
#pragma unroll
            for (int d = 0; d < 4; d++) acc[a][b][d] = 0.0f;

    uint32_t facc[4][8][2];        // fp16x2 chunk accumulators
#pragma unroll
    for (int a = 0; a < 4; a++)
#pragma unroll
        for (int b = 0; b < 8; b++) { facc[a][b][0] = 0u; facc[a][b][1] = 0u; }

    const int prow = (lane >> 2);
    const int pii  = (lane & 3);

    auto load_x = [&](int c, float* xv) {
        const float* xp = x + (size_t)mbase * IDIM + c * 16;
#pragma unroll
        for (int q = 0; q < 8; q++) {
            int grp = wid * 8 + q;
            int row = (grp & 15) * 8 + prow;
            int ii  = (grp >> 4) * 4 + pii;
            xv[q] = xp[row * IDIM + ii];
        }
    };

    auto produce = [&](int s, const float* xv) {
        char* aS = smem + s * A_STAGE;
#pragma unroll
        for (int q = 0; q < 8; q++) {
            int grp = wid * 8 + q;
            int row = (grp & 15) * 8 + prow;
            int ii  = (grp >> 4) * 4 + pii;
            float e  = exp2f(xv[q] * TWO_LOG2E);
            float t  = 1.0f - __fdividef(2.0f, e + 1.0f);
            float t2 = t + t;
            float T1 = t;
            float T2 = __fmaf_rn(t2, T1, -1.0f);
            float T3 = __fmaf_rn(t2, T2, -T1);
            float T4 = __fmaf_rn(t2, T3, -T2);
            float T5 = __fmaf_rn(t2, T4, -T3);
            float T6 = __fmaf_rn(t2, T5, -T4);
            float T7 = __fmaf_rn(t2, T6, -T5);
            float T8 = __fmaf_rn(t2, T7, -T6);
            uint32_t u0, u1, u2, u3;
            { __half2 p = __floats2half2_rn(T1, T2); u0 = *reinterpret_cast<uint32_t*>(&p); }
            { __half2 p = __floats2half2_rn(T3, T4); u1 = *reinterpret_cast<uint32_t*>(&p); }
            { __half2 p = __floats2half2_rn(T5, T6); u2 = *reinterpret_cast<uint32_t*>(&p); }
            { __half2 p = __floats2half2_rn(T7, T8); u3 = *reinterpret_cast<uint32_t*>(&p); }
            *reinterpret_cast<uint4*>(aS + ii * A_PLANE + row * 16) =
                make_uint4(u0, u1, u2, u3);
        }
    };

    auto loadB = [&](int c, int s) {
        const char* src = reinterpret_cast<const char*>(g_B) + (size_t)c * B_STAGE;
        char* dst = smem + SM_B + s * B_STAGE;
#pragma unroll
        for (int r = 0; r < B_STAGE / 16 / THREADS; r++) {   // 16
            int idx = (r * THREADS + tid) * 16;
            asm volatile("cp.async.cg.shared.global [%0], [%1], 16;"
                         :: "r"(s2u(dst + idx)), "l"(src + idx) : "memory");
        }
        asm volatile("cp.async.commit_group;" ::: "memory");
    };

    const int arow = wm * 64 + (lane & 7) + ((lane >> 3) & 1) * 8;
    const int apl  = (lane >> 4);
    const int bcol = wn * 64 + (lane & 7) + ((lane >> 4) & 1) * 8;
    const int bpl  = (lane >> 3) & 1;

    // mma over slices [kk0, kk1): fp16 accumulate into facc
    auto domma = [&](int s, int kk0, int kk1) {
        char* aS = smem + s * A_STAGE;
        char* bS = smem + SM_B + s * B_STAGE;
#pragma unroll
        for (int kk = kk0; kk < kk1; kk++) {
            uint32_t afr[4][4];
#pragma unroll
            for (int mt = 0; mt < 4; mt++) {
                uint32_t ad = s2u(aS + (kk * 2 + apl) * A_PLANE + (arow + mt * 16) * 16);
                asm volatile("ldmatrix.sync.aligned.m8n8.x4.shared.b16 {%0,%1,%2,%3}, [%4];"
                             : "=r"(afr[mt][0]), "=r"(afr[mt][1]),
                               "=r"(afr[mt][2]), "=r"(afr[mt][3]) : "r"(ad));
            }
            uint32_t bfr[4][4];
#pragma unroll
            for (int g = 0; g < 4; g++) {
                uint32_t bd = s2u(bS + (kk * 2 + bpl) * B_PLANE + (bcol + g * 16) * 16);
                asm volatile("ldmatrix.sync.aligned.m8n8.x4.shared.b16 {%0,%1,%2,%3}, [%4];"
                             : "=r"(bfr[g][0]), "=r"(bfr[g][1]),
                               "=r"(bfr[g][2]), "=r"(bfr[g][3]) : "r"(bd));
            }
#pragma unroll
            for (int mt = 0; mt < 4; mt++)
#pragma unroll
                for (int g = 0; g < 4; g++)
#pragma unroll
                    for (int sub = 0; sub < 2; sub++) {
                        uint32_t* d = facc[mt][g * 2 + sub];
                        asm volatile(
                            "mma.sync.aligned.m16n8k16.row.col.f16.f16.f16.f16 "
                            "{%0,%1}, {%2,%3,%4,%5}, {%6,%7}, {%0,%1};"
                            : "+r"(d[0]), "+r"(d[1])
                            : "r"(afr[mt][0]), "r"(afr[mt][1]),
                              "r"(afr[mt][2]), "r"(afr[mt][3]),
                              "r"(bfr[g][sub * 2]), "r"(bfr[g][sub * 2 + 1]));
                    }
        }
    };

    // promote fp16 chunk accumulators into fp32 masters, reset facc
    auto promote = [&]() {
#pragma unroll
        for (int mt = 0; mt < 4; mt++)
#pragma unroll
            for (int nf = 0; nf < 8; nf++) {
#pragma unroll
                for (int h = 0; h < 2; h++) {
                    __half2 hv = *reinterpret_cast<__half2*>(&facc[mt][nf][h]);
                    float2 fv = __half22float2(hv);
                    acc[mt][nf][2 * h + 0] += fv.x;
                    acc[mt][nf][2 * h + 1] += fv.y;
                    facc[mt][nf][h] = 0u;
                }
            }
    };

    // ---- pipeline
    float xv[8], xn[8];
    load_x(0, xv);
    loadB(0, 0);
    produce(0, xv);
    __syncthreads();
    for (int c = 0; c < NCHUNK; c++) {
        int s = c & 1;
        if (c + 1 < NCHUNK) {
            load_x(c + 1, xn);                       // x LDGs in flight
            loadB(c + 1, s ^ 1);
            asm volatile("cp.async.wait_group 1;" ::: "memory");
            domma(s, 0, 4);                          // covers x LDG latency
            produce(s ^ 1, xn);
            domma(s, 4, 8);
        } else {
            asm volatile("cp.async.wait_group 0;" ::: "memory");
            domma(s, 0, 8);
        }
        promote();                                   // once per 128-K chunk
        __syncthreads();
    }

    // ---- epilogue (+ per-o bias)
#pragma unroll
    for (int mt = 0; mt < 4; mt++) {
        int row0 = mbase + wm * 64 + mt * 16 + (lane >> 2);
#pragma unroll
        for (int nf = 0; nf < 8; nf++) {
            int col = wn * 64 + nf * 8 + (lane & 3) * 2;
            float2 bv = *reinterpret_cast<const float2*>(g_bias + col);
            *reinterpret_cast<float2*>(out + (size_t)row0 * ODIM + col) =
                make_float2(acc[mt][nf][0] + bv.x, acc[mt][nf][1] + bv.y);
            *reinterpret_cast<float2*>(out + (size_t)(row0 + 8) * ODIM + col) =
                make_float2(acc[mt][nf][2] + bv.x, acc[mt][nf][3] + bv.y);
        }
    }
}

// ---------------------------------------------------------------- launch
extern "C" void kernel_launch(void* const* d_in, const int* in_sizes, int n_in,
                              void* d_out, int out_size) {
    const float* x       = (const float*)d_in[0];  // [16384, 256]
    const float* weights = (const float*)d_in[1];  // [256, 256]
    const float* coeffs  = (const float*)d_in[2];  // [256, 256, 9]
    float* out = (float*)d_out;                    // [16384, 256] fp32

    cudaFuncSetAttribute(bern_gemm, cudaFuncAttributeMaxDynamicSharedMemorySize,
                         SMEM_TOTAL);

    bern_prep<<<ODIM, IDIM>>>(weights, coeffs);
    bern_gemm<<<BATCH / CTAM, THREADS, SMEM_TOTAL>>>(x, out);
}

// round 11
// speedup vs baseline: 1.1933x; 1.1933x over previous
#include <cuda_runtime.h>
#include <cuda_fp16.h>
#include <cstdint>

// out[b,o] = sum_i f_{o,i}(tanh(x[b,i])), Chebyshev basis, T0 folded to bias.
// GEMM: M=16384, N=256, K=2048 (16 chunks of 128 = 8 k16 slices).
// R11: CTAM 128 -> 112, grid 128 -> 147 (full 148-SM wave; was 20 SMs idle).
//      8 warps x (m112 x n32) warp tiles; tail CTA guarded.

#define BATCH   16384
#define IDIM    256
#define ODIM    256
#define CTAM    112
#define GRID    147                          // ceil(16384/112)
#define NCHUNK  16
#define PLANES  16
#define THREADS 256

#define A_PLANE (CTAM * 16 + 16)             // 1808 (odd 16B stride)
#define A_STAGE (PLANES * A_PLANE)           // 28928
#define B_PLANE (ODIM * 16)                  // 4096
#define B_STAGE (PLANES * B_PLANE)           // 65536
#define SM_B    (2 * A_STAGE)                // 57856
#define SMEM_TOTAL (SM_B + 2 * B_STAGE)      // 188928

#define TWO_LOG2E 2.8853900817779268f

// Chebyshev-basis B operand: [chunk 16][plane 16][col 256][8 halves] = 1 MB
__device__ __align__(128) __half g_B[NCHUNK * PLANES * ODIM * 8];
__device__ float g_bias[ODIM];

__device__ __forceinline__ uint32_t s2u(const void* p) {
    return (uint32_t)__cvta_generic_to_shared(p);
}

// ---------------------------------------------------------------- prep kernel
__global__ void bern_prep(const float* __restrict__ weights,
                          const float* __restrict__ coeffs) {
    static const float M[9][9] = {
        { 1, -8,  28, -56,  70, -56,  28, -8,  1},
        { 1, -6,  14, -14,   0,  14, -14,  6, -1},
        { 1, -4,   4,   4, -10,   4,   4, -4,  1},
        { 1, -2,  -2,   6,   0,  -6,   2,  2, -1},
        { 1,  0,  -4,   0,   6,   0,  -4,  0,  1},
        { 1,  2,  -2,  -6,   0,   6,   2, -2, -1},
        { 1,  4,   4,  -4, -10,  -4,   4,  4,  1},
        { 1,  6,  14,  14,   0, -14, -14, -6, -1},
        { 1,  8,  28,  56,  70,  56,  28,  8,  1}
    };
    int o = blockIdx.x;
    int i = threadIdx.x;

    float w = weights[o * IDIM + i];
    const float* cf = coeffs + (size_t)(o * IDIM + i) * 9;
    float c[9];
#pragma unroll
    for (int k = 0; k < 9; k++) c[k] = cf[k] * w;

    float p[9];
#pragma unroll
    for (int n = 0; n < 9; n++) {
        float s = 0.0f;
#pragma unroll
        for (int k = 0; k < 9; k++) s += c[k] * M[k][n];
        p[n] = s;
    }
    float q0 = p[0] + 0.5f * p[2] + 0.375f * p[4] + 0.3125f * p[6] + 0.2734375f * p[8];
    float q1 = p[1] + 0.75f * p[3] + 0.625f * p[5] + 0.546875f * p[7];
    float q2 = 0.5f * p[2] + 0.5f * p[4] + 0.46875f * p[6] + 0.4375f * p[8];
    float q3 = 0.25f * p[3] + 0.3125f * p[5] + 0.328125f * p[7];
    float q4 = 0.125f * p[4] + 0.1875f * p[6] + 0.21875f * p[8];
    float q5 = 0.0625f * p[5] + 0.109375f * p[7];
    float q6 = 0.03125f * p[6] + 0.0625f * p[8];
    float q7 = 0.015625f * p[7];
    float q8 = 0.0078125f * p[8];

    uint32_t u[4];
    { __half2 h = __floats2half2_rn(q1, q2); u[0] = *reinterpret_cast<uint32_t*>(&h); }
    { __half2 h = __floats2half2_rn(q3, q4); u[1] = *reinterpret_cast<uint32_t*>(&h); }
    { __half2 h = __floats2half2_rn(q5, q6); u[2] = *reinterpret_cast<uint32_t*>(&h); }
    { __half2 h = __floats2half2_rn(q7, q8); u[3] = *reinterpret_cast<uint32_t*>(&h); }
    int cc = i >> 4, pl = i & 15;
    *reinterpret_cast<uint4*>(reinterpret_cast<char*>(g_B) +
        ((size_t)(cc * PLANES + pl) * ODIM + o) * 16) = make_uint4(u[0], u[1], u[2], u[3]);

    __shared__ float red[IDIM];
    red[i] = q0;
    __syncthreads();
#pragma unroll
    for (int st = IDIM / 2; st > 0; st >>= 1) {
        if (i < st) red[i] += red[i + st];
        __syncthreads();
    }
    if (i == 0) g_bias[o] = red[0];
}

// ---------------------------------------------------------------- main kernel
__global__ void __launch_bounds__(THREADS, 1)
bern_gemm(const float* __restrict__ x, float* __restrict__ out) {
    extern __shared__ char smem[];
    const int tid  = threadIdx.x;
    const int wid  = tid >> 5;
    const int lane = tid & 31;
    const int mbase = blockIdx.x * CTAM;
    const int wn = wid;            // 8 warps along N (32 cols each), all share m112

    float acc[7][4][4];
#pragma unroll
    for (int a = 0; a < 7; a++)
#pragma unroll
        for (int b = 0; b < 4; b++)
#pragma unroll
            for (int d = 0; d < 4; d++) acc[a][b][d] = 0.0f;

    // produce tasks: 112 rows x 16 i = 1792 = 256 threads x 7
    auto load_x = [&](int c, float* xv) {
#pragma unroll
        for (int q = 0; q < 7; q++) {
            int task = q * THREADS + tid;
            int row  = task >> 4;
            int ii   = task & 15;
            int rg   = mbase + row;
            if (rg >= BATCH) rg = BATCH - 1;          // tail clamp
            xv[q] = x[(size_t)rg * IDIM + c * 16 + ii];
        }
    };

    auto produce = [&](int s, const float* xv) {
        char* aS = smem + s * A_STAGE;
#pragma unroll
        for (int q = 0; q < 7; q++) {
            int task = q * THREADS + tid;
            int row  = task >> 4;
            int ii   = task & 15;
            float e  = exp2f(xv[q] * TWO_LOG2E);
            float t  = 1.0f - __fdividef(2.0f, e + 1.0f);
            float t2 = t + t;
            float T1 = t;
            float T2 = __fmaf_rn(t2, T1, -1.0f);
            float T3 = __fmaf_rn(t2, T2, -T1);
            float T4 = __fmaf_rn(t2, T3, -T2);
            float T5 = __fmaf_rn(t2, T4, -T3);
            float T6 = __fmaf_rn(t2, T5, -T4);
            float T7 = __fmaf_rn(t2, T6, -T5);
            float T8 = __fmaf_rn(t2, T7, -T6);
            uint32_t u0, u1, u2, u3;
            { __half2 p = __floats2half2_rn(T1, T2); u0 = *reinterpret_cast<uint32_t*>(&p); }
            { __half2 p = __floats2half2_rn(T3, T4); u1 = *reinterpret_cast<uint32_t*>(&p); }
            { __half2 p = __floats2half2_rn(T5, T6); u2 = *reinterpret_cast<uint32_t*>(&p); }
            { __half2 p = __floats2half2_rn(T7, T8); u3 = *reinterpret_cast<uint32_t*>(&p); }
            *reinterpret_cast<uint4*>(aS + ii * A_PLANE + row * 16) =
                make_uint4(u0, u1, u2, u3);
        }
    };

    auto loadB = [&](int c, int s) {
        const char* src = reinterpret_cast<const char*>(g_B) + (size_t)c * B_STAGE;
        char* dst = smem + SM_B + s * B_STAGE;
#pragma unroll
        for (int r = 0; r < B_STAGE / 16 / THREADS; r++) {   // 16
            int idx = (r * THREADS + tid) * 16;
            asm volatile("cp.async.cg.shared.global [%0], [%1], 16;"
                         :: "r"(s2u(dst + idx)), "l"(src + idx) : "memory");
        }
        asm volatile("cp.async.commit_group;" ::: "memory");
    };

    const int arow = (lane & 7) + ((lane >> 3) & 1) * 8;
    const int apl  = (lane >> 4);
    const int bcol = wn * 32 + (lane & 7) + ((lane >> 4) & 1) * 8;
    const int bpl  = (lane >> 3) & 1;

    auto domma = [&](int s, int kk0, int kk1) {
        char* aS = smem + s * A_STAGE;
        char* bS = smem + SM_B + s * B_STAGE;
#pragma unroll
        for (int kk = kk0; kk < kk1; kk++) {
            uint32_t afr[7][4];
#pragma unroll
            for (int mt = 0; mt < 7; mt++) {
                uint32_t ad = s2u(aS + (kk * 2 + apl) * A_PLANE + (arow + mt * 16) * 16);
                asm volatile("ldmatrix.sync.aligned.m8n8.x4.shared.b16 {%0,%1,%2,%3}, [%4];"
                             : "=r"(afr[mt][0]), "=r"(afr[mt][1]),
                               "=r"(afr[mt][2]), "=r"(afr[mt][3]) : "r"(ad));
            }
            uint32_t bfr[2][4];
#pragma unroll
            for (int g = 0; g < 2; g++) {
                uint32_t bd = s2u(bS + (kk * 2 + bpl) * B_PLANE + (bcol + g * 16) * 16);
                asm volatile("ldmatrix.sync.aligned.m8n8.x4.shared.b16 {%0,%1,%2,%3}, [%4];"
                             : "=r"(bfr[g][0]), "=r"(bfr[g][1]),
                               "=r"(bfr[g][2]), "=r"(bfr[g][3]) : "r"(bd));
            }
#pragma unroll
            for (int mt = 0; mt < 7; mt++)
#pragma unroll
                for (int g = 0; g < 2; g++)
#pragma unroll
                    for (int sub = 0; sub < 2; sub++) {
                        float* d = acc[mt][g * 2 + sub];
                        asm volatile(
                            "mma.sync.aligned.m16n8k16.row.col.f32.f16.f16.f32 "
                            "{%0,%1,%2,%3}, {%4,%5,%6,%7}, {%8,%9}, {%0,%1,%2,%3};"
                            : "+f"(d[0]), "+f"(d[1]), "+f"(d[2]), "+f"(d[3])
                            : "r"(afr[mt][0]), "r"(afr[mt][1]),
                              "r"(afr[mt][2]), "r"(afr[mt][3]),
                              "r"(bfr[g][sub * 2]), "r"(bfr[g][sub * 2 + 1]));
                    }
        }
    };

    // ---- pipeline
    float xv[7], xn[7];
    load_x(0, xv);
    loadB(0, 0);
    produce(0, xv);
    __syncthreads();
    for (int c = 0; c < NCHUNK; c++) {
        int s = c & 1;
        if (c + 1 < NCHUNK) {
            load_x(c + 1, xn);                       // x LDGs in flight
            loadB(c + 1, s ^ 1);
            asm volatile("cp.async.wait_group 1;" ::: "memory");
            domma(s, 0, 4);                          // covers x LDG latency
            produce(s ^ 1, xn);
            domma(s, 4, 8);
        } else {
            asm volatile("cp.async.wait_group 0;" ::: "memory");
            domma(s, 0, 8);
        }
        __syncthreads();
    }

    // ---- epilogue (+ per-o bias), tail rows guarded
#pragma unroll
    for (int mt = 0; mt < 7; mt++) {
        int row0 = mbase + mt * 16 + (lane >> 2);
#pragma unroll
        for (int nf = 0; nf < 4; nf++) {
            int col = wn * 32 + nf * 8 + (lane & 3) * 2;
            float2 bv = *reinterpret_cast<const float2*>(g_bias + col);
            if (row0 < BATCH)
                *reinterpret_cast<float2*>(out + (size_t)row0 * ODIM + col) =
                    make_float2(acc[mt][nf][0] + bv.x, acc[mt][nf][1] + bv.y);
            if (row0 + 8 < BATCH)
                *reinterpret_cast<float2*>(out + (size_t)(row0 + 8) * ODIM + col) =
                    make_float2(acc[mt][nf][2] + bv.x, acc[mt][nf][3] + bv.y);
        }
    }
}

// ---------------------------------------------------------------- launch
extern "C" void kernel_launch(void* const* d_in, const int* in_sizes, int n_in,
                              void* d_out, int out_size) {
    const float* x       = (const float*)d_in[0];  // [16384, 256]
    const float* weights = (const float*)d_in[1];  // [256, 256]
    const float* coeffs  = (const float*)d_in[2];  // [256, 256, 9]
    float* out = (float*)d_out;                    // [16384, 256] fp32

    cudaFuncSetAttribute(bern_gemm, cudaFuncAttributeMaxDynamicSharedMemorySize,
                         SMEM_TOTAL);

    bern_prep<<<ODIM, IDIM>>>(weights, coeffs);
    bern_gemm<<<GRID, THREADS, SMEM_TOTAL>>>(x, out);
}

// round 12
// speedup vs baseline: 1.2487x; 1.0464x over previous
#include <cuda_runtime.h>
#include <cuda_fp16.h>
#include <cstdint>

// out[b,o] = sum_i f_{o,i}(tanh(x[b,i])), Chebyshev basis, T0 folded to bias.
// GEMM: M=16384, N=256, K=2048 (16 chunks of 128 = 8 k16 slices).
// R12: warp-specialized: 8 MMA warps + 2 producer warps, mbarrier handoff,
//      no __syncthreads in the mainloop. CTAM=112, grid=147 (full wave).

#define BATCH   16384
#define IDIM    256
#define ODIM    256
#define CTAM    112
#define GRID    147
#define NCHUNK  16
#define PLANES  16
#define THREADS 320                          // 8 MMA warps + 2 producer warps

#define A_PLANE (CTAM * 16 + 16)             // 1808
#define A_STAGE (PLANES * A_PLANE)           // 28928
#define B_PLANE (ODIM * 16)                  // 4096
#define B_STAGE (PLANES * B_PLANE)           // 65536
#define SM_B    (2 * A_STAGE)                // 57856
#define SM_BAR  (SM_B + 2 * B_STAGE)         // 188928
#define SMEM_TOTAL (SM_BAR + 32)             // 188960

#define TWO_LOG2E 2.8853900817779268f

__device__ __align__(128) __half g_B[NCHUNK * PLANES * ODIM * 8];
__device__ float g_bias[ODIM];

__device__ __forceinline__ uint32_t s2u(const void* p) {
    return (uint32_t)__cvta_generic_to_shared(p);
}
__device__ __forceinline__ void mbar_init(uint32_t m, uint32_t cnt) {
    asm volatile("mbarrier.init.shared.b64 [%0], %1;" :: "r"(m), "r"(cnt) : "memory");
}
__device__ __forceinline__ void mbar_arrive(uint32_t m) {
    asm volatile("mbarrier.arrive.shared.b64 _, [%0];" :: "r"(m) : "memory");
}
__device__ __forceinline__ void mbar_wait(uint32_t m, uint32_t parity) {
    asm volatile(
        "{\n\t.reg .pred P;\n\t"
        "W_%=:\n\t"
        "mbarrier.try_wait.parity.acquire.cta.shared::cta.b64 P, [%0], %1, 0x989680;\n\t"
        "@P bra.uni D_%=;\n\t"
        "bra.uni W_%=;\n\t"
        "D_%=:\n\t}"
        :: "r"(m), "r"(parity) : "memory");
}

// ---------------------------------------------------------------- prep kernel
__global__ void bern_prep(const float* __restrict__ weights,
                          const float* __restrict__ coeffs) {
    static const float M[9][9] = {
        { 1, -8,  28, -56,  70, -56,  28, -8,  1},
        { 1, -6,  14, -14,   0,  14, -14,  6, -1},
        { 1, -4,   4,   4, -10,   4,   4, -4,  1},
        { 1, -2,  -2,   6,   0,  -6,   2,  2, -1},
        { 1,  0,  -4,   0,   6,   0,  -4,  0,  1},
        { 1,  2,  -2,  -6,   0,   6,   2, -2, -1},
        { 1,  4,   4,  -4, -10,  -4,   4,  4,  1},
        { 1,  6,  14,  14,   0, -14, -14, -6, -1},
        { 1,  8,  28,  56,  70,  56,  28,  8,  1}
    };
    int o = blockIdx.x;
    int i = threadIdx.x;

    float w = weights[o * IDIM + i];
    const float* cf = coeffs + (size_t)(o * IDIM + i) * 9;
    float c[9];
#pragma unroll
    for (int k = 0; k < 9; k++) c[k] = cf[k] * w;

    float p[9];
#pragma unroll
    for (int n = 0; n < 9; n++) {
        float s = 0.0f;
#pragma unroll
        for (int k = 0; k < 9; k++) s += c[k] * M[k][n];
        p[n] = s;
    }
    float q0 = p[0] + 0.5f * p[2] + 0.375f * p[4] + 0.3125f * p[6] + 0.2734375f * p[8];
    float q1 = p[1] + 0.75f * p[3] + 0.625f * p[5] + 0.546875f * p[7];
    float q2 = 0.5f * p[2] + 0.5f * p[4] + 0.46875f * p[6] + 0.4375f * p[8];
    float q3 = 0.25f * p[3] + 0.3125f * p[5] + 0.328125f * p[7];
    float q4 = 0.125f * p[4] + 0.1875f * p[6] + 0.21875f * p[8];
    float q5 = 0.0625f * p[5] + 0.109375f * p[7];
    float q6 = 0.03125f * p[6] + 0.0625f * p[8];
    float q7 = 0.015625f * p[7];
    float q8 = 0.0078125f * p[8];

    uint32_t u[4];
    { __half2 h = __floats2half2_rn(q1, q2); u[0] = *reinterpret_cast<uint32_t*>(&h); }
    { __half2 h = __floats2half2_rn(q3, q4); u[1] = *reinterpret_cast<uint32_t*>(&h); }
    { __half2 h = __floats2half2_rn(q5, q6); u[2] = *reinterpret_cast<uint32_t*>(&h); }
    { __half2 h = __floats2half2_rn(q7, q8); u[3] = *reinterpret_cast<uint32_t*>(&h); }
    int cc = i >> 4, pl = i & 15;
    *reinterpret_cast<uint4*>(reinterpret_cast<char*>(g_B) +
        ((size_t)(cc * PLANES + pl) * ODIM + o) * 16) = make_uint4(u[0], u[1], u[2], u[3]);

    __shared__ float red[IDIM];
    red[i] = q0;
    __syncthreads();
#pragma unroll
    for (int st = IDIM / 2; st > 0; st >>= 1) {
        if (i < st) red[i] += red[i + st];
        __syncthreads();
    }
    if (i == 0) g_bias[o] = red[0];
}

// ---------------------------------------------------------------- main kernel
__global__ void __launch_bounds__(THREADS, 1)
bern_gemm(const float* __restrict__ x, float* __restrict__ out) {
    extern __shared__ char smem[];
    const uint32_t smem_u = s2u(smem);
    const int tid  = threadIdx.x;
    const int wid  = tid >> 5;
    const int lane = tid & 31;
    const int mbase = blockIdx.x * CTAM;

    const uint32_t bar_full  = smem_u + SM_BAR;        // 2 x 8B
    const uint32_t bar_empty = smem_u + SM_BAR + 16;   // 2 x 8B

    if (tid == 0) {
        mbar_init(bar_full + 0, 64);   // 64 producer threads arrive
        mbar_init(bar_full + 8, 64);
        mbar_init(bar_empty + 0, 8);   // 8 MMA warps (lane 0) arrive
        mbar_init(bar_empty + 8, 8);
        // pre-arm both empties through phase 0
#pragma unroll
        for (int j = 0; j < 8; j++) { mbar_arrive(bar_empty + 0); mbar_arrive(bar_empty + 8); }
    }
    __syncthreads();

    if (wid >= 8) {
        // ======================= producer warps (64 threads)
        const int ptid = tid - 256;    // 0..63
        for (int c = 0; c < NCHUNK; c++) {
            const int s = c & 1, ph = (c >> 1) & 1;
            mbar_wait(bar_empty + 8 * s, ph);

            // B: 4096 x 16B cp.async, 64 per thread
            const char* src = reinterpret_cast<const char*>(g_B) + (size_t)c * B_STAGE;
            char* dstB = smem + SM_B + s * B_STAGE;
#pragma unroll 8
            for (int r = 0; r < 64; r++) {
                int idx = (r * 64 + ptid) * 16;
                asm volatile("cp.async.cg.shared.global [%0], [%1], 16;"
                             :: "r"(s2u(dstB + idx)), "l"(src + idx) : "memory");
            }
            asm volatile("cp.async.commit_group;" ::: "memory");

            // A: 1792 tasks, 28 per thread, in 4 batches of 7 (xv in regs)
            char* aS = smem + s * A_STAGE;
#pragma unroll
            for (int bt = 0; bt < 4; bt++) {
                float xv[7];
#pragma unroll
                for (int q = 0; q < 7; q++) {
                    int task = (bt * 7 + q) * 64 + ptid;
                    int row  = task >> 4;
                    int rg   = mbase + row; if (rg >= BATCH) rg = BATCH - 1;
                    xv[q] = x[(size_t)rg * IDIM + c * 16 + (task & 15)];
                }
#pragma unroll
                for (int q = 0; q < 7; q++) {
                    int task = (bt * 7 + q) * 64 + ptid;
                    int row  = task >> 4;
                    int ii   = task & 15;
                    float e  = exp2f(xv[q] * TWO_LOG2E);
                    float t  = 1.0f - __fdividef(2.0f, e + 1.0f);
                    float t2 = t + t;
                    float T1 = t;
                    float T2 = __fmaf_rn(t2, T1, -1.0f);
                    float T3 = __fmaf_rn(t2, T2, -T1);
                    float T4 = __fmaf_rn(t2, T3, -T2);
                    float T5 = __fmaf_rn(t2, T4, -T3);
                    float T6 = __fmaf_rn(t2, T5, -T4);
                    float T7 = __fmaf_rn(t2, T6, -T5);
                    float T8 = __fmaf_rn(t2, T7, -T6);
                    uint32_t u0, u1, u2, u3;
                    { __half2 p = __floats2half2_rn(T1, T2); u0 = *reinterpret_cast<uint32_t*>(&p); }
                    { __half2 p = __floats2half2_rn(T3, T4); u1 = *reinterpret_cast<uint32_t*>(&p); }
                    { __half2 p = __floats2half2_rn(T5, T6); u2 = *reinterpret_cast<uint32_t*>(&p); }
                    { __half2 p = __floats2half2_rn(T7, T8); u3 = *reinterpret_cast<uint32_t*>(&p); }
                    *reinterpret_cast<uint4*>(aS + ii * A_PLANE + row * 16) =
                        make_uint4(u0, u1, u2, u3);
                }
            }
            asm volatile("cp.async.wait_group 0;" ::: "memory");
            mbar_arrive(bar_full + 8 * s);
        }
    } else {
        // ======================= MMA warps (8 warps, wn = wid)
        const int wn = wid;
        float acc[7][4][4];
#pragma unroll
        for (int a = 0; a < 7; a++)
#pragma unroll
            for (int b = 0; b < 4; b++)
#pragma unroll
                for (int d = 0; d < 4; d++) acc[a][b][d] = 0.0f;

        const int arow = (lane & 7) + ((lane >> 3) & 1) * 8;
        const int apl  = (lane >> 4);
        const int bcol = wn * 32 + (lane & 7) + ((lane >> 4) & 1) * 8;
        const int bpl  = (lane >> 3) & 1;

        for (int c = 0; c < NCHUNK; c++) {
            const int s = c & 1, ph = (c >> 1) & 1;
            mbar_wait(bar_full + 8 * s, ph);
            char* aS = smem + s * A_STAGE;
            char* bS = smem + SM_B + s * B_STAGE;
#pragma unroll
            for (int kk = 0; kk < 8; kk++) {
                uint32_t afr[7][4];
#pragma unroll
                for (int mt = 0; mt < 7; mt++) {
                    uint32_t ad = s2u(aS + (kk * 2 + apl) * A_PLANE + (arow + mt * 16) * 16);
                    asm volatile("ldmatrix.sync.aligned.m8n8.x4.shared.b16 {%0,%1,%2,%3}, [%4];"
                                 : "=r"(afr[mt][0]), "=r"(afr[mt][1]),
                                   "=r"(afr[mt][2]), "=r"(afr[mt][3]) : "r"(ad));
                }
                uint32_t bfr[2][4];
#pragma unroll
                for (int g = 0; g < 2; g++) {
                    uint32_t bd = s2u(bS + (kk * 2 + bpl) * B_PLANE + (bcol + g * 16) * 16);
                    asm volatile("ldmatrix.sync.aligned.m8n8.x4.shared.b16 {%0,%1,%2,%3}, [%4];"
                                 : "=r"(bfr[g][0]), "=r"(bfr[g][1]),
                                   "=r"(bfr[g][2]), "=r"(bfr[g][3]) : "r"(bd));
                }
#pragma unroll
                for (int mt = 0; mt < 7; mt++)
#pragma unroll
                    for (int g = 0; g < 2; g++)
#pragma unroll
                        for (int sub = 0; sub < 2; sub++) {
                            float* d = acc[mt][g * 2 + sub];
                            asm volatile(
                                "mma.sync.aligned.m16n8k16.row.col.f32.f16.f16.f32 "
                                "{%0,%1,%2,%3}, {%4,%5,%6,%7}, {%8,%9}, {%0,%1,%2,%3};"
                                : "+f"(d[0]), "+f"(d[1]), "+f"(d[2]), "+f"(d[3])
                                : "r"(afr[mt][0]), "r"(afr[mt][1]),
                                  "r"(afr[mt][2]), "r"(afr[mt][3]),
                                  "r"(bfr[g][sub * 2]), "r"(bfr[g][sub * 2 + 1]));
                        }
            }
            __syncwarp();
            if (lane == 0) mbar_arrive(bar_empty + 8 * s);
        }

        // ---- epilogue (+ per-o bias), tail rows guarded
#pragma unroll
        for (int mt = 0; mt < 7; mt++) {
            int row0 = mbase + mt * 16 + (lane >> 2);
#pragma unroll
            for (int nf = 0; nf < 4; nf++) {
                int col = wn * 32 + nf * 8 + (lane & 3) * 2;
                float2 bv = *reinterpret_cast<const float2*>(g_bias + col);
                if (row0 < BATCH)
                    *reinterpret_cast<float2*>(out + (size_t)row0 * ODIM + col) =
                        make_float2(acc[mt][nf][0] + bv.x, acc[mt][nf][1] + bv.y);
                if (row0 + 8 < BATCH)
                    *reinterpret_cast<float2*>(out + (size_t)(row0 + 8) * ODIM + col) =
                        make_float2(acc[mt][nf][2] + bv.x, acc[mt][nf][3] + bv.y);
            }
        }
    }
}

// ---------------------------------------------------------------- launch
extern "C" void kernel_launch(void* const* d_in, const int* in_sizes, int n_in,
                              void* d_out, int out_size) {
    const float* x       = (const float*)d_in[0];  // [16384, 256]
    const float* weights = (const float*)d_in[1];  // [256, 256]
    const float* coeffs  = (const float*)d_in[2];  // [256, 256, 9]
    float* out = (float*)d_out;                    // [16384, 256] fp32

    cudaFuncSetAttribute(bern_gemm, cudaFuncAttributeMaxDynamicSharedMemorySize,
                         SMEM_TOTAL);

    bern_prep<<<ODIM, IDIM>>>(weights, coeffs);
    bern_gemm<<<GRID, THREADS, SMEM_TOTAL>>>(x, out);
}

// round 13
// speedup vs baseline: 1.3534x; 1.0838x over previous
#include <cuda_runtime.h>
#include <cuda_fp16.h>
#include <cstdint>

// out[b,o] = sum_i f_{o,i}(tanh(x[b,i])), Chebyshev basis, T0 folded to bias.
// GEMM: M=16384, N=256, K=2048 (16 chunks of 128 = 8 k16 slices).
// R13: 4 producer warps (was 2) + x LDGs issued BEFORE the empty-barrier wait
//      so DRAM latency overlaps the wait; producer now ~1k cyc/chunk vs
//      consumer ~3.1k -> MMA warps never starve.

#define BATCH   16384
#define IDIM    256
#define ODIM    256
#define CTAM    112
#define GRID    147
#define NCHUNK  16
#define PLANES  16
#define THREADS 384                          // 8 MMA warps + 4 producer warps

#define A_PLANE (CTAM * 16 + 16)             // 1808
#define A_STAGE (PLANES * A_PLANE)           // 28928
#define B_PLANE (ODIM * 16)                  // 4096
#define B_STAGE (PLANES * B_PLANE)           // 65536
#define SM_B    (2 * A_STAGE)                // 57856
#define SM_BAR  (SM_B + 2 * B_STAGE)         // 188928
#define SMEM_TOTAL (SM_BAR + 32)             // 188960

#define TWO_LOG2E 2.8853900817779268f

__device__ __align__(128) __half g_B[NCHUNK * PLANES * ODIM * 8];
__device__ float g_bias[ODIM];

__device__ __forceinline__ uint32_t s2u(const void* p) {
    return (uint32_t)__cvta_generic_to_shared(p);
}
__device__ __forceinline__ void mbar_init(uint32_t m, uint32_t cnt) {
    asm volatile("mbarrier.init.shared.b64 [%0], %1;" :: "r"(m), "r"(cnt) : "memory");
}
__device__ __forceinline__ void mbar_arrive(uint32_t m) {
    asm volatile("mbarrier.arrive.shared.b64 _, [%0];" :: "r"(m) : "memory");
}
__device__ __forceinline__ void mbar_wait(uint32_t m, uint32_t parity) {
    asm volatile(
        "{\n\t.reg .pred P;\n\t"
        "W_%=:\n\t"
        "mbarrier.try_wait.parity.acquire.cta.shared::cta.b64 P, [%0], %1, 0x989680;\n\t"
        "@P bra.uni D_%=;\n\t"
        "bra.uni W_%=;\n\t"
        "D_%=:\n\t}"
        :: "r"(m), "r"(parity) : "memory");
}

// ---------------------------------------------------------------- prep kernel
__global__ void bern_prep(const float* __restrict__ weights,
                          const float* __restrict__ coeffs) {
    static const float M[9][9] = {
        { 1, -8,  28, -56,  70, -56,  28, -8,  1},
        { 1, -6,  14, -14,   0,  14, -14,  6, -1},
        { 1, -4,   4,   4, -10,   4,   4, -4,  1},
        { 1, -2,  -2,   6,   0,  -6,   2,  2, -1},
        { 1,  0,  -4,   0,   6,   0,  -4,  0,  1},
        { 1,  2,  -2,  -6,   0,   6,   2, -2, -1},
        { 1,  4,   4,  -4, -10,  -4,   4,  4,  1},
        { 1,  6,  14,  14,   0, -14, -14, -6, -1},
        { 1,  8,  28,  56,  70,  56,  28,  8,  1}
    };
    int o = blockIdx.x;
    int i = threadIdx.x;

    float w = weights[o * IDIM + i];
    const float* cf = coeffs + (size_t)(o * IDIM + i) * 9;
    float c[9];
#pragma unroll
    for (int k = 0; k < 9; k++) c[k] = cf[k] * w;

    float p[9];
#pragma unroll
    for (int n = 0; n < 9; n++) {
        float s = 0.0f;
#pragma unroll
        for (int k = 0; k < 9; k++) s += c[k] * M[k][n];
        p[n] = s;
    }
    float q0 = p[0] + 0.5f * p[2] + 0.375f * p[4] + 0.3125f * p[6] + 0.2734375f * p[8];
    float q1 = p[1] + 0.75f * p[3] + 0.625f * p[5] + 0.546875f * p[7];
    float q2 = 0.5f * p[2] + 0.5f * p[4] + 0.46875f * p[6] + 0.4375f * p[8];
    float q3 = 0.25f * p[3] + 0.3125f * p[5] + 0.328125f * p[7];
    float q4 = 0.125f * p[4] + 0.1875f * p[6] + 0.21875f * p[8];
    float q5 = 0.0625f * p[5] + 0.109375f * p[7];
    float q6 = 0.03125f * p[6] + 0.0625f * p[8];
    float q7 = 0.015625f * p[7];
    float q8 = 0.0078125f * p[8];

    uint32_t u[4];
    { __half2 h = __floats2half2_rn(q1, q2); u[0] = *reinterpret_cast<uint32_t*>(&h); }
    { __half2 h = __floats2half2_rn(q3, q4); u[1] = *reinterpret_cast<uint32_t*>(&h); }
    { __half2 h = __floats2half2_rn(q5, q6); u[2] = *reinterpret_cast<uint32_t*>(&h); }
    { __half2 h = __floats2half2_rn(q7, q8); u[3] = *reinterpret_cast<uint32_t*>(&h); }
    int cc = i >> 4, pl = i & 15;
    *reinterpret_cast<uint4*>(reinterpret_cast<char*>(g_B) +
        ((size_t)(cc * PLANES + pl) * ODIM + o) * 16) = make_uint4(u[0], u[1], u[2], u[3]);

    __shared__ float red[IDIM];
    red[i] = q0;
    __syncthreads();
#pragma unroll
    for (int st = IDIM / 2; st > 0; st >>= 1) {
        if (i < st) red[i] += red[i + st];
        __syncthreads();
    }
    if (i == 0) g_bias[o] = red[0];
}

// ---------------------------------------------------------------- main kernel
__global__ void __launch_bounds__(THREADS, 1)
bern_gemm(const float* __restrict__ x, float* __restrict__ out) {
    extern __shared__ char smem[];
    const uint32_t smem_u = s2u(smem);
    const int tid  = threadIdx.x;
    const int wid  = tid >> 5;
    const int lane = tid & 31;
    const int mbase = blockIdx.x * CTAM;

    const uint32_t bar_full  = smem_u + SM_BAR;        // 2 x 8B
    const uint32_t bar_empty = smem_u + SM_BAR + 16;   // 2 x 8B

    if (tid == 0) {
        mbar_init(bar_full + 0, 128);  // 128 producer threads arrive
        mbar_init(bar_full + 8, 128);
        mbar_init(bar_empty + 0, 8);   // 8 MMA warps (lane 0) arrive
        mbar_init(bar_empty + 8, 8);
#pragma unroll
        for (int j = 0; j < 8; j++) { mbar_arrive(bar_empty + 0); mbar_arrive(bar_empty + 8); }
    }
    __syncthreads();

    if (wid >= 8) {
        // ======================= producer warps (4 warps, 128 threads)
        const int ptid = tid - 256;    // 0..127
        for (int c = 0; c < NCHUNK; c++) {
            const int s = c & 1, ph = (c >> 1) & 1;

            // x LDGs FIRST (register dests; safe before the stage is empty).
            // Latency overlaps the empty wait + B issue below.
            float xv[14];
#pragma unroll
            for (int q = 0; q < 14; q++) {
                int task = q * 128 + ptid;
                int row  = task >> 4;
                int rg   = mbase + row; if (rg >= BATCH) rg = BATCH - 1;
                xv[q] = x[(size_t)rg * IDIM + c * 16 + (task & 15)];
            }

            mbar_wait(bar_empty + 8 * s, ph);

            // B: 4096 x 16B cp.async, 32 per thread
            const char* src = reinterpret_cast<const char*>(g_B) + (size_t)c * B_STAGE;
            char* dstB = smem + SM_B + s * B_STAGE;
#pragma unroll 8
            for (int r = 0; r < 32; r++) {
                int idx = (r * 128 + ptid) * 16;
                asm volatile("cp.async.cg.shared.global [%0], [%1], 16;"
                             :: "r"(s2u(dstB + idx)), "l"(src + idx) : "memory");
            }
            asm volatile("cp.async.commit_group;" ::: "memory");

            // A: 14 tasks per thread, x already in registers
            char* aS = smem + s * A_STAGE;
#pragma unroll
            for (int q = 0; q < 14; q++) {
                int task = q * 128 + ptid;
                int row  = task >> 4;
                int ii   = task & 15;
                float e  = exp2f(xv[q] * TWO_LOG2E);
                float t  = 1.0f - __fdividef(2.0f, e + 1.0f);
                float t2 = t + t;
                float T1 = t;
                float T2 = __fmaf_rn(t2, T1, -1.0f);
                float T3 = __fmaf_rn(t2, T2, -T1);
                float T4 = __fmaf_rn(t2, T3, -T2);
                float T5 = __fmaf_rn(t2, T4, -T3);
                float T6 = __fmaf_rn(t2, T5, -T4);
                float T7 = __fmaf_rn(t2, T6, -T5);
                float T8 = __fmaf_rn(t2, T7, -T6);
                uint32_t u0, u1, u2, u3;
                { __half2 p = __floats2half2_rn(T1, T2); u0 = *reinterpret_cast<uint32_t*>(&p); }
                { __half2 p = __floats2half2_rn(T3, T4); u1 = *reinterpret_cast<uint32_t*>(&p); }
                { __half2 p = __floats2half2_rn(T5, T6); u2 = *reinterpret_cast<uint32_t*>(&p); }
                { __half2 p = __floats2half2_rn(T7, T8); u3 = *reinterpret_cast<uint32_t*>(&p); }
                *reinterpret_cast<uint4*>(aS + ii * A_PLANE + row * 16) =
                    make_uint4(u0, u1, u2, u3);
            }
            asm volatile("cp.async.wait_group 0;" ::: "memory");
            mbar_arrive(bar_full + 8 * s);
        }
    } else {
        // ======================= MMA warps (8 warps, wn = wid)
        const int wn = wid;
        float acc[7][4][4];
#pragma unroll
        for (int a = 0; a < 7; a++)
#pragma unroll
            for (int b = 0; b < 4; b++)
#pragma unroll
                for (int d = 0; d < 4; d++) acc[a][b][d] = 0.0f;

        const int arow = (lane & 7) + ((lane >> 3) & 1) * 8;
        const int apl  = (lane >> 4);
        const int bcol = wn * 32 + (lane & 7) + ((lane >> 4) & 1) * 8;
        const int bpl  = (lane >> 3) & 1;

        for (int c = 0; c < NCHUNK; c++) {
            const int s = c & 1, ph = (c >> 1) & 1;
            mbar_wait(bar_full + 8 * s, ph);
            char* aS = smem + s * A_STAGE;
            char* bS = smem + SM_B + s * B_STAGE;
#pragma unroll
            for (int kk = 0; kk < 8; kk++) {
                uint32_t afr[7][4];
#pragma unroll
                for (int mt = 0; mt < 7; mt++) {
                    uint32_t ad = s2u(aS + (kk * 2 + apl) * A_PLANE + (arow + mt * 16) * 16);
                    asm volatile("ldmatrix.sync.aligned.m8n8.x4.shared.b16 {%0,%1,%2,%3}, [%4];"
                                 : "=r"(afr[mt][0]), "=r"(afr[mt][1]),
                                   "=r"(afr[mt][2]), "=r"(afr[mt][3]) : "r"(ad));
                }
                uint32_t bfr[2][4];
#pragma unroll
                for (int g = 0; g < 2; g++) {
                    uint32_t bd = s2u(bS + (kk * 2 + bpl) * B_PLANE + (bcol + g * 16) * 16);
                    asm volatile("ldmatrix.sync.aligned.m8n8.x4.shared.b16 {%0,%1,%2,%3}, [%4];"
                                 : "=r"(bfr[g][0]), "=r"(bfr[g][1]),
                                   "=r"(bfr[g][2]), "=r"(bfr[g][3]) : "r"(bd));
                }
#pragma unroll
                for (int mt = 0; mt < 7; mt++)
#pragma unroll
                    for (int g = 0; g < 2; g++)
#pragma unroll
                        for (int sub = 0; sub < 2; sub++) {
                            float* d = acc[mt][g * 2 + sub];
                            asm volatile(
                                "mma.sync.aligned.m16n8k16.row.col.f32.f16.f16.f32 "
                                "{%0,%1,%2,%3}, {%4,%5,%6,%7}, {%8,%9}, {%0,%1,%2,%3};"
                                : "+f"(d[0]), "+f"(d[1]), "+f"(d[2]), "+f"(d[3])
                                : "r"(afr[mt][0]), "r"(afr[mt][1]),
                                  "r"(afr[mt][2]), "r"(afr[mt][3]),
                                  "r"(bfr[g][sub * 2]), "r"(bfr[g][sub * 2 + 1]));
                        }
            }
            __syncwarp();
            if (lane == 0) mbar_arrive(bar_empty + 8 * s);
        }

        // ---- epilogue (+ per-o bias), tail rows guarded
#pragma unroll
        for (int mt = 0; mt < 7; mt++) {
            int row0 = mbase + mt * 16 + (lane >> 2);
#pragma unroll
            for (int nf = 0; nf < 4; nf++) {
                int col = wn * 32 + nf * 8 + (lane & 3) * 2;
                float2 bv = *reinterpret_cast<const float2*>(g_bias + col);
                if (row0 < BATCH)
                    *reinterpret_cast<float2*>(out + (size_t)row0 * ODIM + col) =
                        make_float2(acc[mt][nf][0] + bv.x, acc[mt][nf][1] + bv.y);
                if (row0 + 8 < BATCH)
                    *reinterpret_cast<float2*>(out + (size_t)(row0 + 8) * ODIM + col) =
                        make_float2(acc[mt][nf][2] + bv.x, acc[mt][nf][3] + bv.y);
            }
        }
    }
}

// ---------------------------------------------------------------- launch
extern "C" void kernel_launch(void* const* d_in, const int* in_sizes, int n_in,
                              void* d_out, int out_size) {
    const float* x       = (const float*)d_in[0];  // [16384, 256]
    const float* weights = (const float*)d_in[1];  // [256, 256]
    const float* coeffs  = (const float*)d_in[2];  // [256, 256, 9]
    float* out = (float*)d_out;                    // [16384, 256] fp32

    cudaFuncSetAttribute(bern_gemm, cudaFuncAttributeMaxDynamicSharedMemorySize,
                         SMEM_TOTAL);

    bern_prep<<<ODIM, IDIM>>>(weights, coeffs);
    bern_gemm<<<GRID, THREADS, SMEM_TOTAL>>>(x, out);
}

// round 14
// speedup vs baseline: 1.3610x; 1.0056x over previous
#include <cuda_runtime.h>
#include <cuda_fp16.h>
#include <cstdint>

// out[b,o] = sum_i f_{o,i}(tanh(x[b,i])), Chebyshev basis, T0 folded to bias.
// GEMM: M=16384, N=256, K=2048 (16 chunks of 128 = 8 k16 slices).
// R14: cross-slice B-fragment prefetch (fills LDSM->HMMA bubbles at slice
//      heads), __syncwarp removed; everything else as R13.

#define BATCH   16384
#define IDIM    256
#define ODIM    256
#define CTAM    112
#define GRID    147
#define NCHUNK  16
#define PLANES  16
#define THREADS 384                          // 8 MMA warps + 4 producer warps

#define A_PLANE (CTAM * 16 + 16)             // 1808
#define A_STAGE (PLANES * A_PLANE)           // 28928
#define B_PLANE (ODIM * 16)                  // 4096
#define B_STAGE (PLANES * B_PLANE)           // 65536
#define SM_B    (2 * A_STAGE)                // 57856
#define SM_BAR  (SM_B + 2 * B_STAGE)         // 188928
#define SMEM_TOTAL (SM_BAR + 32)             // 188960

#define TWO_LOG2E 2.8853900817779268f

__device__ __align__(128) __half g_B[NCHUNK * PLANES * ODIM * 8];
__device__ float g_bias[ODIM];

__device__ __forceinline__ uint32_t s2u(const void* p) {
    return (uint32_t)__cvta_generic_to_shared(p);
}
__device__ __forceinline__ void mbar_init(uint32_t m, uint32_t cnt) {
    asm volatile("mbarrier.init.shared.b64 [%0], %1;" :: "r"(m), "r"(cnt) : "memory");
}
__device__ __forceinline__ void mbar_arrive(uint32_t m) {
    asm volatile("mbarrier.arrive.shared.b64 _, [%0];" :: "r"(m) : "memory");
}
__device__ __forceinline__ void mbar_wait(uint32_t m, uint32_t parity) {
    asm volatile(
        "{\n\t.reg .pred P;\n\t"
        "W_%=:\n\t"
        "mbarrier.try_wait.parity.acquire.cta.shared::cta.b64 P, [%0], %1, 0x989680;\n\t"
        "@P bra.uni D_%=;\n\t"
        "bra.uni W_%=;\n\t"
        "D_%=:\n\t}"
        :: "r"(m), "r"(parity) : "memory");
}

// ---------------------------------------------------------------- prep kernel
__global__ void bern_prep(const float* __restrict__ weights,
                          const float* __restrict__ coeffs) {
    static const float M[9][9] = {
        { 1, -8,  28, -56,  70, -56,  28, -8,  1},
        { 1, -6,  14, -14,   0,  14, -14,  6, -1},
        { 1, -4,   4,   4, -10,   4,   4, -4,  1},
        { 1, -2,  -2,   6,   0,  -6,   2,  2, -1},
        { 1,  0,  -4,   0,   6,   0,  -4,  0,  1},
        { 1,  2,  -2,  -6,   0,   6,   2, -2, -1},
        { 1,  4,   4,  -4, -10,  -4,   4,  4,  1},
        { 1,  6,  14,  14,   0, -14, -14, -6, -1},
        { 1,  8,  28,  56,  70,  56,  28,  8,  1}
    };
    int o = blockIdx.x;
    int i = threadIdx.x;

    float w = weights[o * IDIM + i];
    const float* cf = coeffs + (size_t)(o * IDIM + i) * 9;
    float c[9];
#pragma unroll
    for (int k = 0; k < 9; k++) c[k] = cf[k] * w;

    float p[9];
#pragma unroll
    for (int n = 0; n < 9; n++) {
        float s = 0.0f;
#pragma unroll
        for (int k = 0; k < 9; k++) s += c[k] * M[k][n];
        p[n] = s;
    }
    float q0 = p[0] + 0.5f * p[2] + 0.375f * p[4] + 0.3125f * p[6] + 0.2734375f * p[8];
    float q1 = p[1] + 0.75f * p[3] + 0.625f * p[5] + 0.546875f * p[7];
    float q2 = 0.5f * p[2] + 0.5f * p[4] + 0.46875f * p[6] + 0.4375f * p[8];
    float q3 = 0.25f * p[3] + 0.3125f * p[5] + 0.328125f * p[7];
    float q4 = 0.125f * p[4] + 0.1875f * p[6] + 0.21875f * p[8];
    float q5 = 0.0625f * p[5] + 0.109375f * p[7];
    float q6 = 0.03125f * p[6] + 0.0625f * p[8];
    float q7 = 0.015625f * p[7];
    float q8 = 0.0078125f * p[8];

    uint32_t u[4];
    { __half2 h = __floats2half2_rn(q1, q2); u[0] = *reinterpret_cast<uint32_t*>(&h); }
    { __half2 h = __floats2half2_rn(q3, q4); u[1] = *reinterpret_cast<uint32_t*>(&h); }
    { __half2 h = __floats2half2_rn(q5, q6); u[2] = *reinterpret_cast<uint32_t*>(&h); }
    { __half2 h = __floats2half2_rn(q7, q8); u[3] = *reinterpret_cast<uint32_t*>(&h); }
    int cc = i >> 4, pl = i & 15;
    *reinterpret_cast<uint4*>(reinterpret_cast<char*>(g_B) +
        ((size_t)(cc * PLANES + pl) * ODIM + o) * 16) = make_uint4(u[0], u[1], u[2], u[3]);

    __shared__ float red[IDIM];
    red[i] = q0;
    __syncthreads();
#pragma unroll
    for (int st = IDIM / 2; st > 0; st >>= 1) {
        if (i < st) red[i] += red[i + st];
        __syncthreads();
    }
    if (i == 0) g_bias[o] = red[0];
}

// ---------------------------------------------------------------- main kernel
__global__ void __launch_bounds__(THREADS, 1)
bern_gemm(const float* __restrict__ x, float* __restrict__ out) {
    extern __shared__ char smem[];
    const uint32_t smem_u = s2u(smem);
    const int tid  = threadIdx.x;
    const int wid  = tid >> 5;
    const int lane = tid & 31;
    const int mbase = blockIdx.x * CTAM;

    const uint32_t bar_full  = smem_u + SM_BAR;        // 2 x 8B
    const uint32_t bar_empty = smem_u + SM_BAR + 16;   // 2 x 8B

    if (tid == 0) {
        mbar_init(bar_full + 0, 128);  // 128 producer threads arrive
        mbar_init(bar_full + 8, 128);
        mbar_init(bar_empty + 0, 8);   // 8 MMA warps (lane 0) arrive
        mbar_init(bar_empty + 8, 8);
#pragma unroll
        for (int j = 0; j < 8; j++) { mbar_arrive(bar_empty + 0); mbar_arrive(bar_empty + 8); }
    }
    __syncthreads();

    if (wid >= 8) {
        // ======================= producer warps (4 warps, 128 threads)
        const int ptid = tid - 256;    // 0..127
        for (int c = 0; c < NCHUNK; c++) {
            const int s = c & 1, ph = (c >> 1) & 1;

            // x LDGs first: latency overlaps the empty wait + B issue below.
            float xv[14];
#pragma unroll
            for (int q = 0; q < 14; q++) {
                int task = q * 128 + ptid;
                int row  = task >> 4;
                int rg   = mbase + row; if (rg >= BATCH) rg = BATCH - 1;
                xv[q] = x[(size_t)rg * IDIM + c * 16 + (task & 15)];
            }

            mbar_wait(bar_empty + 8 * s, ph);

            // B: 4096 x 16B cp.async, 32 per thread
            const char* src = reinterpret_cast<const char*>(g_B) + (size_t)c * B_STAGE;
            char* dstB = smem + SM_B + s * B_STAGE;
#pragma unroll 8
            for (int r = 0; r < 32; r++) {
                int idx = (r * 128 + ptid) * 16;
                asm volatile("cp.async.cg.shared.global [%0], [%1], 16;"
                             :: "r"(s2u(dstB + idx)), "l"(src + idx) : "memory");
            }
            asm volatile("cp.async.commit_group;" ::: "memory");

            // A: 14 tasks per thread, x already in registers
            char* aS = smem + s * A_STAGE;
#pragma unroll
            for (int q = 0; q < 14; q++) {
                int task = q * 128 + ptid;
                int row  = task >> 4;
                int ii   = task & 15;
                float e  = exp2f(xv[q] * TWO_LOG2E);
                float t  = 1.0f - __fdividef(2.0f, e + 1.0f);
                float t2 = t + t;
                float T1 = t;
                float T2 = __fmaf_rn(t2, T1, -1.0f);
                float T3 = __fmaf_rn(t2, T2, -T1);
                float T4 = __fmaf_rn(t2, T3, -T2);
                float T5 = __fmaf_rn(t2, T4, -T3);
                float T6 = __fmaf_rn(t2, T5, -T4);
                float T7 = __fmaf_rn(t2, T6, -T5);
                float T8 = __fmaf_rn(t2, T7, -T6);
                uint32_t u0, u1, u2, u3;
                { __half2 p = __floats2half2_rn(T1, T2); u0 = *reinterpret_cast<uint32_t*>(&p); }
                { __half2 p = __floats2half2_rn(T3, T4); u1 = *reinterpret_cast<uint32_t*>(&p); }
                { __half2 p = __floats2half2_rn(T5, T6); u2 = *reinterpret_cast<uint32_t*>(&p); }
                { __half2 p = __floats2half2_rn(T7, T8); u3 = *reinterpret_cast<uint32_t*>(&p); }
                *reinterpret_cast<uint4*>(aS + ii * A_PLANE + row * 16) =
                    make_uint4(u0, u1, u2, u3);
            }
            asm volatile("cp.async.wait_group 0;" ::: "memory");
            mbar_arrive(bar_full + 8 * s);
        }
    } else {
        // ======================= MMA warps (8 warps, wn = wid)
        const int wn = wid;
        float acc[7][4][4];
#pragma unroll
        for (int a = 0; a < 7; a++)
#pragma unroll
            for (int b = 0; b < 4; b++)
#pragma unroll
                for (int d = 0; d < 4; d++) acc[a][b][d] = 0.0f;

        const int arow = (lane & 7) + ((lane >> 3) & 1) * 8;
        const int apl  = (lane >> 4);
        const int bcol = wn * 32 + (lane & 7) + ((lane >> 4) & 1) * 8;
        const int bpl  = (lane >> 3) & 1;

        for (int c = 0; c < NCHUNK; c++) {
            const int s = c & 1, ph = (c >> 1) & 1;
            mbar_wait(bar_full + 8 * s, ph);
            char* aS = smem + s * A_STAGE;
            char* bS = smem + SM_B + s * B_STAGE;

            // prefetch B fragments of slice 0
            uint32_t bfr[2][2][4];
#pragma unroll
            for (int g = 0; g < 2; g++) {
                uint32_t bd = s2u(bS + bpl * B_PLANE + (bcol + g * 16) * 16);
                asm volatile("ldmatrix.sync.aligned.m8n8.x4.shared.b16 {%0,%1,%2,%3}, [%4];"
                             : "=r"(bfr[0][g][0]), "=r"(bfr[0][g][1]),
                               "=r"(bfr[0][g][2]), "=r"(bfr[0][g][3]) : "r"(bd));
            }
#pragma unroll
            for (int kk = 0; kk < 8; kk++) {
                const int cur = kk & 1;
                uint32_t afr[7][4];
#pragma unroll
                for (int mt = 0; mt < 7; mt++) {
                    uint32_t ad = s2u(aS + (kk * 2 + apl) * A_PLANE + (arow + mt * 16) * 16);
                    asm volatile("ldmatrix.sync.aligned.m8n8.x4.shared.b16 {%0,%1,%2,%3}, [%4];"
                                 : "=r"(afr[mt][0]), "=r"(afr[mt][1]),
                                   "=r"(afr[mt][2]), "=r"(afr[mt][3]) : "r"(ad));
                }
                if (kk < 7) {
                    // prefetch next slice's B under this slice's HMMAs
#pragma unroll
                    for (int g = 0; g < 2; g++) {
                        uint32_t bd = s2u(bS + ((kk + 1) * 2 + bpl) * B_PLANE +
                                          (bcol + g * 16) * 16);
                        asm volatile("ldmatrix.sync.aligned.m8n8.x4.shared.b16 {%0,%1,%2,%3}, [%4];"
                                     : "=r"(bfr[cur ^ 1][g][0]), "=r"(bfr[cur ^ 1][g][1]),
                                       "=r"(bfr[cur ^ 1][g][2]), "=r"(bfr[cur ^ 1][g][3])
                                     : "r"(bd));
                    }
                }
#pragma unroll
                for (int mt = 0; mt < 7; mt++)
#pragma unroll
                    for (int g = 0; g < 2; g++)
#pragma unroll
                        for (int sub = 0; sub < 2; sub++) {
                            float* d = acc[mt][g * 2 + sub];
                            asm volatile(
                                "mma.sync.aligned.m16n8k16.row.col.f32.f16.f16.f32 "
                                "{%0,%1,%2,%3}, {%4,%5,%6,%7}, {%8,%9}, {%0,%1,%2,%3};"
                                : "+f"(d[0]), "+f"(d[1]), "+f"(d[2]), "+f"(d[3])
                                : "r"(afr[mt][0]), "r"(afr[mt][1]),
                                  "r"(afr[mt][2]), "r"(afr[mt][3]),
                                  "r"(bfr[cur][g][sub * 2]), "r"(bfr[cur][g][sub * 2 + 1]));
                        }
            }
            if (lane == 0) mbar_arrive(bar_empty + 8 * s);
        }

        // ---- epilogue (+ per-o bias), tail rows guarded
#pragma unroll
        for (int mt = 0; mt < 7; mt++) {
            int row0 = mbase + mt * 16 + (lane >> 2);
#pragma unroll
            for (int nf = 0; nf < 4; nf++) {
                int col = wn * 32 + nf * 8 + (lane & 3) * 2;
                float2 bv = *reinterpret_cast<const float2*>(g_bias + col);
                if (row0 < BATCH)
                    *reinterpret_cast<float2*>(out + (size_t)row0 * ODIM + col) =
                        make_float2(acc[mt][nf][0] + bv.x, acc[mt][nf][1] + bv.y);
                if (row0 + 8 < BATCH)
                    *reinterpret_cast<float2*>(out + (size_t)(row0 + 8) * ODIM + col) =
                        make_float2(acc[mt][nf][2] + bv.x, acc[mt][nf][3] + bv.y);
            }
        }
    }
}

// ---------------------------------------------------------------- launch
extern "C" void kernel_launch(void* const* d_in, const int* in_sizes, int n_in,
                              void* d_out, int out_size) {
    const float* x       = (const float*)d_in[0];  // [16384, 256]
    const float* weights = (const float*)d_in[1];  // [256, 256]
    const float* coeffs  = (const float*)d_in[2];  // [256, 256, 9]
    float* out = (float*)d_out;                    // [16384, 256] fp32

    cudaFuncSetAttribute(bern_gemm, cudaFuncAttributeMaxDynamicSharedMemorySize,
                         SMEM_TOTAL);

    bern_prep<<<ODIM, IDIM>>>(weights, coeffs);
    bern_gemm<<<GRID, THREADS, SMEM_TOTAL>>>(x, out);
}

// round 15
// speedup vs baseline: 1.3619x; 1.0007x over previous
#include <cuda_runtime.h>
#include <cuda_fp16.h>
#include <cstdint>

// out[b,o] = sum_i f_{o,i}(tanh(x[b,i])), Chebyshev basis, T0 folded to bias.
// GEMM: M=16384, N=256, K=2048 (16 chunks of 128 = 8 k16 slices).
// R15: mt-granular software pipeline in the consumer — every LDSM is issued
//      between HMMA groups, no burst-LDSM window at slice heads. Base: R13.

#define BATCH   16384
#define IDIM    256
#define ODIM    256
#define CTAM    112
#define GRID    147
#define NCHUNK  16
#define PLANES  16
#define THREADS 384                          // 8 MMA warps + 4 producer warps

#define A_PLANE (CTAM * 16 + 16)             // 1808
#define A_STAGE (PLANES * A_PLANE)           // 28928
#define B_PLANE (ODIM * 16)                  // 4096
#define B_STAGE (PLANES * B_PLANE)           // 65536
#define SM_B    (2 * A_STAGE)                // 57856
#define SM_BAR  (SM_B + 2 * B_STAGE)         // 188928
#define SMEM_TOTAL (SM_BAR + 32)             // 188960

#define TWO_LOG2E 2.8853900817779268f

__device__ __align__(128) __half g_B[NCHUNK * PLANES * ODIM * 8];
__device__ float g_bias[ODIM];

__device__ __forceinline__ uint32_t s2u(const void* p) {
    return (uint32_t)__cvta_generic_to_shared(p);
}
__device__ __forceinline__ void mbar_init(uint32_t m, uint32_t cnt) {
    asm volatile("mbarrier.init.shared.b64 [%0], %1;" :: "r"(m), "r"(cnt) : "memory");
}
__device__ __forceinline__ void mbar_arrive(uint32_t m) {
    asm volatile("mbarrier.arrive.shared.b64 _, [%0];" :: "r"(m) : "memory");
}
__device__ __forceinline__ void mbar_wait(uint32_t m, uint32_t parity) {
    asm volatile(
        "{\n\t.reg .pred P;\n\t"
        "W_%=:\n\t"
        "mbarrier.try_wait.parity.acquire.cta.shared::cta.b64 P, [%0], %1, 0x989680;\n\t"
        "@P bra.uni D_%=;\n\t"
        "bra.uni W_%=;\n\t"
        "D_%=:\n\t}"
        :: "r"(m), "r"(parity) : "memory");
}

// ---------------------------------------------------------------- prep kernel
__global__ void bern_prep(const float* __restrict__ weights,
                          const float* __restrict__ coeffs) {
    static const float M[9][9] = {
        { 1, -8,  28, -56,  70, -56,  28, -8,  1},
        { 1, -6,  14, -14,   0,  14, -14,  6, -1},
        { 1, -4,   4,   4, -10,   4,   4, -4,  1},
        { 1, -2,  -2,   6,   0,  -6,   2,  2, -1},
        { 1,  0,  -4,   0,   6,   0,  -4,  0,  1},
        { 1,  2,  -2,  -6,   0,   6,   2, -2, -1},
        { 1,  4,   4,  -4, -10,  -4,   4,  4,  1},
        { 1,  6,  14,  14,   0, -14, -14, -6, -1},
        { 1,  8,  28,  56,  70,  56,  28,  8,  1}
    };
    int o = blockIdx.x;
    int i = threadIdx.x;

    float w = weights[o * IDIM + i];
    const float* cf = coeffs + (size_t)(o * IDIM + i) * 9;
    float c[9];
#pragma unroll
    for (int k = 0; k < 9; k++) c[k] = cf[k] * w;

    float p[9];
#pragma unroll
    for (int n = 0; n < 9; n++) {
        float s = 0.0f;
#pragma unroll
        for (int k = 0; k < 9; k++) s += c[k] * M[k][n];
        p[n] = s;
    }
    float q0 = p[0] + 0.5f * p[2] + 0.375f * p[4] + 0.3125f * p[6] + 0.2734375f * p[8];
    float q1 = p[1] + 0.75f * p[3] + 0.625f * p[5] + 0.546875f * p[7];
    float q2 = 0.5f * p[2] + 0.5f * p[4] + 0.46875f * p[6] + 0.4375f * p[8];
    float q3 = 0.25f * p[3] + 0.3125f * p[5] + 0.328125f * p[7];
    float q4 = 0.125f * p[4] + 0.1875f * p[6] + 0.21875f * p[8];
    float q5 = 0.0625f * p[5] + 0.109375f * p[7];
    float q6 = 0.03125f * p[6] + 0.0625f * p[8];
    float q7 = 0.015625f * p[7];
    float q8 = 0.0078125f * p[8];

    uint32_t u[4];
    { __half2 h = __floats2half2_rn(q1, q2); u[0] = *reinterpret_cast<uint32_t*>(&h); }
    { __half2 h = __floats2half2_rn(q3, q4); u[1] = *reinterpret_cast<uint32_t*>(&h); }
    { __half2 h = __floats2half2_rn(q5, q6); u[2] = *reinterpret_cast<uint32_t*>(&h); }
    { __half2 h = __floats2half2_rn(q7, q8); u[3] = *reinterpret_cast<uint32_t*>(&h); }
    int cc = i >> 4, pl = i & 15;
    *reinterpret_cast<uint4*>(reinterpret_cast<char*>(g_B) +
        ((size_t)(cc * PLANES + pl) * ODIM + o) * 16) = make_uint4(u[0], u[1], u[2], u[3]);

    __shared__ float red[IDIM];
    red[i] = q0;
    __syncthreads();
#pragma unroll
    for (int st = IDIM / 2; st > 0; st >>= 1) {
        if (i < st) red[i] += red[i + st];
        __syncthreads();
    }
    if (i == 0) g_bias[o] = red[0];
}

// ---------------------------------------------------------------- main kernel
__global__ void __launch_bounds__(THREADS, 1)
bern_gemm(const float* __restrict__ x, float* __restrict__ out) {
    extern __shared__ char smem[];
    const uint32_t smem_u = s2u(smem);
    const int tid  = threadIdx.x;
    const int wid  = tid >> 5;
    const int lane = tid & 31;
    const int mbase = blockIdx.x * CTAM;

    const uint32_t bar_full  = smem_u + SM_BAR;        // 2 x 8B
    const uint32_t bar_empty = smem_u + SM_BAR + 16;   // 2 x 8B

    if (tid == 0) {
        mbar_init(bar_full + 0, 128);  // 128 producer threads arrive
        mbar_init(bar_full + 8, 128);
        mbar_init(bar_empty + 0, 8);   // 8 MMA warps (lane 0) arrive
        mbar_init(bar_empty + 8, 8);
#pragma unroll
        for (int j = 0; j < 8; j++) { mbar_arrive(bar_empty + 0); mbar_arrive(bar_empty + 8); }
    }
    __syncthreads();

    if (wid >= 8) {
        // ======================= producer warps (4 warps, 128 threads)
        const int ptid = tid - 256;    // 0..127
        for (int c = 0; c < NCHUNK; c++) {
            const int s = c & 1, ph = (c >> 1) & 1;

            // x LDGs first: latency overlaps the empty wait + B issue below.
            float xv[14];
#pragma unroll
            for (int q = 0; q < 14; q++) {
                int task = q * 128 + ptid;
                int row  = task >> 4;
                int rg   = mbase + row; if (rg >= BATCH) rg = BATCH - 1;
                xv[q] = x[(size_t)rg * IDIM + c * 16 + (task & 15)];
            }

            mbar_wait(bar_empty + 8 * s, ph);

            // B: 4096 x 16B cp.async, 32 per thread
            const char* src = reinterpret_cast<const char*>(g_B) + (size_t)c * B_STAGE;
            char* dstB = smem + SM_B + s * B_STAGE;
#pragma unroll 8
            for (int r = 0; r < 32; r++) {
                int idx = (r * 128 + ptid) * 16;
                asm volatile("cp.async.cg.shared.global [%0], [%1], 16;"
                             :: "r"(s2u(dstB + idx)), "l"(src + idx) : "memory");
            }
            asm volatile("cp.async.commit_group;" ::: "memory");

            // A: 14 tasks per thread, x already in registers
            char* aS = smem + s * A_STAGE;
#pragma unroll
            for (int q = 0; q < 14; q++) {
                int task = q * 128 + ptid;
                int row  = task >> 4;
                int ii   = task & 15;
                float e  = exp2f(xv[q] * TWO_LOG2E);
                float t  = 1.0f - __fdividef(2.0f, e + 1.0f);
                float t2 = t + t;
                float T1 = t;
                float T2 = __fmaf_rn(t2, T1, -1.0f);
                float T3 = __fmaf_rn(t2, T2, -T1);
                float T4 = __fmaf_rn(t2, T3, -T2);
                float T5 = __fmaf_rn(t2, T4, -T3);
                float T6 = __fmaf_rn(t2, T5, -T4);
                float T7 = __fmaf_rn(t2, T6, -T5);
                float T8 = __fmaf_rn(t2, T7, -T6);
                uint32_t u0, u1, u2, u3;
                { __half2 p = __floats2half2_rn(T1, T2); u0 = *reinterpret_cast<uint32_t*>(&p); }
                { __half2 p = __floats2half2_rn(T3, T4); u1 = *reinterpret_cast<uint32_t*>(&p); }
                { __half2 p = __floats2half2_rn(T5, T6); u2 = *reinterpret_cast<uint32_t*>(&p); }
                { __half2 p = __floats2half2_rn(T7, T8); u3 = *reinterpret_cast<uint32_t*>(&p); }
                *reinterpret_cast<uint4*>(aS + ii * A_PLANE + row * 16) =
                    make_uint4(u0, u1, u2, u3);
            }
            asm volatile("cp.async.wait_group 0;" ::: "memory");
            mbar_arrive(bar_full + 8 * s);
        }
    } else {
        // ======================= MMA warps (8 warps, wn = wid)
        const int wn = wid;
        float acc[7][4][4];
#pragma unroll
        for (int a = 0; a < 7; a++)
#pragma unroll
            for (int b = 0; b < 4; b++)
#pragma unroll
                for (int d = 0; d < 4; d++) acc[a][b][d] = 0.0f;

        const int arow = (lane & 7) + ((lane >> 3) & 1) * 8;
        const int apl  = (lane >> 4);
        const int bcol = wn * 32 + (lane & 7) + ((lane >> 4) & 1) * 8;
        const int bpl  = (lane >> 3) & 1;

        for (int c = 0; c < NCHUNK; c++) {
            const int s = c & 1, ph = (c >> 1) & 1;
            mbar_wait(bar_full + 8 * s, ph);
            char* aS = smem + s * A_STAGE;
            char* bS = smem + SM_B + s * B_STAGE;
#pragma unroll
            for (int kk = 0; kk < 8; kk++) {
                // B fragments for this slice (2 LDSM)
                uint32_t bfr[2][4];
#pragma unroll
                for (int g = 0; g < 2; g++) {
                    uint32_t bd = s2u(bS + (kk * 2 + bpl) * B_PLANE + (bcol + g * 16) * 16);
                    asm volatile("ldmatrix.sync.aligned.m8n8.x4.shared.b16 {%0,%1,%2,%3}, [%4];"
                                 : "=r"(bfr[g][0]), "=r"(bfr[g][1]),
                                   "=r"(bfr[g][2]), "=r"(bfr[g][3]) : "r"(bd));
                }
                // mt-granular pipeline: afr double-buffered at mt level; each
                // LDSM is issued between HMMA groups, never in a burst.
                uint32_t afr[2][4];
                {
                    uint32_t ad = s2u(aS + (kk * 2 + apl) * A_PLANE + arow * 16);
                    asm volatile("ldmatrix.sync.aligned.m8n8.x4.shared.b16 {%0,%1,%2,%3}, [%4];"
                                 : "=r"(afr[0][0]), "=r"(afr[0][1]),
                                   "=r"(afr[0][2]), "=r"(afr[0][3]) : "r"(ad));
                }
#pragma unroll
                for (int mt = 0; mt < 7; mt++) {
                    const int cur = mt & 1;
                    if (mt < 6) {
                        uint32_t ad = s2u(aS + (kk * 2 + apl) * A_PLANE +
                                          (arow + (mt + 1) * 16) * 16);
                        asm volatile("ldmatrix.sync.aligned.m8n8.x4.shared.b16 {%0,%1,%2,%3}, [%4];"
                                     : "=r"(afr[cur ^ 1][0]), "=r"(afr[cur ^ 1][1]),
                                       "=r"(afr[cur ^ 1][2]), "=r"(afr[cur ^ 1][3]) : "r"(ad));
                    }
#pragma unroll
                    for (int g = 0; g < 2; g++)
#pragma unroll
                        for (int sub = 0; sub < 2; sub++) {
                            float* d = acc[mt][g * 2 + sub];
                            asm volatile(
                                "mma.sync.aligned.m16n8k16.row.col.f32.f16.f16.f32 "
                                "{%0,%1,%2,%3}, {%4,%5,%6,%7}, {%8,%9}, {%0,%1,%2,%3};"
                                : "+f"(d[0]), "+f"(d[1]), "+f"(d[2]), "+f"(d[3])
                                : "r"(afr[cur][0]), "r"(afr[cur][1]),
                                  "r"(afr[cur][2]), "r"(afr[cur][3]),
                                  "r"(bfr[g][sub * 2]), "r"(bfr[g][sub * 2 + 1]));
                        }
                }
            }
            if (lane == 0) mbar_arrive(bar_empty + 8 * s);
        }

        // ---- epilogue (+ per-o bias), tail rows guarded
#pragma unroll
        for (int mt = 0; mt < 7; mt++) {
            int row0 = mbase + mt * 16 + (lane >> 2);
#pragma unroll
            for (int nf = 0; nf < 4; nf++) {
                int col = wn * 32 + nf * 8 + (lane & 3) * 2;
                float2 bv = *reinterpret_cast<const float2*>(g_bias + col);
                if (row0 < BATCH)
                    *reinterpret_cast<float2*>(out + (size_t)row0 * ODIM + col) =
                        make_float2(acc[mt][nf][0] + bv.x, acc[mt][nf][1] + bv.y);
                if (row0 + 8 < BATCH)
                    *reinterpret_cast<float2*>(out + (size_t)(row0 + 8) * ODIM + col) =
                        make_float2(acc[mt][nf][2] + bv.x, acc[mt][nf][3] + bv.y);
            }
        }
    }
}

// ---------------------------------------------------------------- launch
extern "C" void kernel_launch(void* const* d_in, const int* in_sizes, int n_in,
                              void* d_out, int out_size) {
    const float* x       = (const float*)d_in[0];  // [16384, 256]
    const float* weights = (const float*)d_in[1];  // [256, 256]
    const float* coeffs  = (const float*)d_in[2];  // [256, 256, 9]
    float* out = (float*)d_out;                    // [16384, 256] fp32

    cudaFuncSetAttribute(bern_gemm, cudaFuncAttributeMaxDynamicSharedMemorySize,
                         SMEM_TOTAL);

    bern_prep<<<ODIM, IDIM>>>(weights, coeffs);
    bern_gemm<<<GRID, THREADS, SMEM_TOTAL>>>(x, out);
}